// round 16
// baseline (speedup 1.0000x reference)
#include <cuda_runtime.h>
#include <cuda_bf16.h>

#define TPB 64         // halved again: finest load-balance granularity (single change vs R15)
#define RPT 4          // anchors per thread
#define MAXA 256       // smem GT capacity (A=64 here; +1 pad slot used)

__global__ __launch_bounds__(TPB)
void AssignClsLabel_kernel(const float4* __restrict__ anchors,
                           const float4* __restrict__ gts,
                           const int* __restrict__ counts,
                           const int* __restrict__ use_anchor_p,
                           float* __restrict__ out,
                           int N, int A, int blocksPerBatch) {
    __shared__ float4 sg4[MAXA + 1];   // compacted (gy1, gx1, gy2, gx2) + pad
    __shared__ float  sga[MAXA + 1];   // compacted gt area + pad
    __shared__ float  sredmax[TPB / 32], sredmin[TPB / 32];
    __shared__ int    scnt;

    const int b   = blockIdx.x / blocksPerBatch;
    const int blk = blockIdx.x - b * blocksPerBatch;
    const int cnt = counts[b];
    const int ua  = use_anchor_p ? use_anchor_p[0] : 1;
    const int tid = threadIdx.x;
    const int base = blk * (TPB * RPT) + tid;

    // ---- Load anchors, derive corners + area (bit-identical to reference) ----
    float y1[RPT], y2[RPT], x1[RPT], x2[RPT], ar[RPT];
    float amax = -1e30f, amin = 1e30f;
    #pragma unroll
    for (int r = 0; r < RPT; r++) {
        int idx = base + r * TPB;
        // OOB sentinel: never overlaps, never positive, never in band.
        y1[r] = 4e9f; y2[r] = 4e9f; x1[r] = 4e9f; x2[r] = 4e9f; ar[r] = 1.f;
        if (idx < N) {
            float4 a = anchors[(size_t)b * N + idx];
            if (ua) {
                y1[r] = a.x - 0.5f * a.z;   // 0.5*h exact => contraction-safe
                y2[r] = y1[r] + a.z;
                x1[r] = a.y - 0.5f * a.w;
                x2[r] = x1[r] + a.w;
                ar[r] = __fmul_rn(a.z, a.w);
            } else {
                y1[r] = a.x; x1[r] = a.y; y2[r] = a.z; x2[r] = a.w;
                ar[r] = __fmul_rn(__fsub_rn(a.z, a.x), __fsub_rn(a.w, a.y));
            }
            amax = fmaxf(amax, ar[r]);
            amin = fminf(amin, ar[r]);
        }
    }

    // ---- Block-wide anchor-area min/max for exact GT pruning ----
    #pragma unroll
    for (int off = 16; off > 0; off >>= 1) {
        amax = fmaxf(amax, __shfl_xor_sync(0xffffffffu, amax, off));
        amin = fminf(amin, __shfl_xor_sync(0xffffffffu, amin, off));
    }
    if ((tid & 31) == 0) { sredmax[tid >> 5] = amax; sredmin[tid >> 5] = amin; }
    if (tid == 0) scnt = 0;
    __syncthreads();
    amax = sredmax[0]; amin = sredmin[0];
    #pragma unroll
    for (int w = 1; w < TPB / 32; w++) {
        amax = fmaxf(amax, sredmax[w]);
        amin = fminf(amin, sredmin[w]);
    }
    // iou>=0.5 requires area/2 <= ga <= 2*area (inter <= min(area,ga),
    // 3*inter >= area+ga). 0.5% slack >> fp rounding: prune is label-exact.
    const float gaHi = 2.01f * amax;
    const float gaLo = amin * (1.0f / 2.01f);

    // ---- Stage + compact valid, matchable GTs into smem ----
    for (int g = tid; g < cnt; g += TPB) {
        float4 v = gts[(size_t)b * A + g];
        float ga = __fmul_rn(__fsub_rn(v.z, v.x), __fsub_rn(v.w, v.y));
        if (ga <= gaHi && ga >= gaLo) {
            int p = atomicAdd(&scnt, 1);
            sg4[p] = v; sga[p] = ga;
        }
    }
    __syncthreads();
    const int m = scnt;
    // Even-pad with duplicate of GT 0: max-accumulation is idempotent,
    // so the duplicate cannot change any label.
    if (tid == 0 && (m & 1)) { sg4[m] = sg4[0]; sga[m] = sga[0]; }
    __syncthreads();
    const int m2 = (m + 1) & ~1;

    // ---- Main loop: identical FP body to champion; 2 GTs per trip ----
    // cond: iou>=0.5 <=> 3*inter >= ar+ga <=> w = fma(3,inter,-ga) >= ar (reals)
    float wm[RPT];
    #pragma unroll
    for (int r = 0; r < RPT; r++) wm[r] = -1e30f;

    for (int g = 0; g < m2; g += 2) {
        const float4 va  = sg4[g];
        const float  gaa = sga[g];
        const float4 vb  = sg4[g + 1];
        const float  gab = sga[g + 1];
        #pragma unroll
        for (int r = 0; r < RPT; r++) {
            // dy clamped; dx unclamped: dx<0 => inter<=0 => w<=-ga, safely negative.
            float dy    = fmaxf(0.f, __fsub_rn(fminf(y2[r], va.z), fmaxf(y1[r], va.x)));
            float dx    = __fsub_rn(fminf(x2[r], va.w), fmaxf(x1[r], va.y));
            float inter = __fmul_rn(dy, dx);            // bit-identical to ref (overlap)
            float w     = __fmaf_rn(3.0f, inter, -gaa); // single rounding
            wm[r] = fmaxf(wm[r], w);
        }
        #pragma unroll
        for (int r = 0; r < RPT; r++) {
            float dy    = fmaxf(0.f, __fsub_rn(fminf(y2[r], vb.z), fmaxf(y1[r], vb.x)));
            float dx    = __fsub_rn(fminf(x2[r], vb.w), fmaxf(x1[r], vb.y));
            float inter = __fmul_rn(dy, dx);
            float w     = __fmaf_rn(3.0f, inter, -gab);
            wm[r] = fmaxf(wm[r], w);
        }
    }

    // ---- Classify; rare band hits -> literal bit-exact fallback ----
    #pragma unroll
    for (int r = 0; r < RPT; r++) {
        int idx = base + r * TPB;
        if (idx >= N) continue;
        // band = 2^-21*(ar+gaHi): >=6x the ref-chain (uni + cr-div) slack.
        float band = 4.76837158203125e-7f * (ar[r] + gaHi);
        float lab;
        if (wm[r] >= ar[r] + band) {
            lab = 1.0f;
        } else if (wm[r] <= ar[r] - band) {
            lab = 0.0f;
        } else {
            lab = 0.0f;   // literal reference recompute over ALL valid GTs
            for (int g = 0; g < cnt; g++) {
                float4 v2 = gts[(size_t)b * A + g];
                float ga2 = __fmul_rn(__fsub_rn(v2.z, v2.x), __fsub_rn(v2.w, v2.y));
                float yy1 = fminf(fmaxf(y1[r], v2.x), v2.z);
                float yy2 = fminf(fmaxf(y2[r], v2.x), v2.z);
                float xx1 = fminf(fmaxf(x1[r], v2.y), v2.w);
                float xx2 = fminf(fmaxf(x2[r], v2.y), v2.w);
                float it  = __fmul_rn(__fsub_rn(yy2, yy1), __fsub_rn(xx2, xx1));
                float uni = __fsub_rn(__fadd_rn(ar[r], ga2), it);
                if (__fdiv_rn(it, uni) >= 0.5f) { lab = 1.0f; break; }
            }
        }
        out[(size_t)b * N + idx] = lab;
    }
}

extern "C" void kernel_launch(void* const* d_in, const int* in_sizes, int n_in,
                              void* d_out, int out_size) {
    // Bind by size signature: anchors = largest; gts = 2nd largest;
    // of the rest, counts = larger (B elems), use_anchor = smaller (optional).
    int ia = 0;
    for (int i = 1; i < n_in; i++) if (in_sizes[i] > in_sizes[ia]) ia = i;
    int ig = -1;
    for (int i = 0; i < n_in; i++) {
        if (i == ia) continue;
        if (ig < 0 || in_sizes[i] > in_sizes[ig]) ig = i;
    }
    int ic = -1, iu = -1;
    for (int i = 0; i < n_in; i++) {
        if (i == ia || i == ig) continue;
        if (ic < 0) ic = i;
        else if (in_sizes[i] > in_sizes[ic]) { iu = ic; ic = i; }
        else iu = i;
    }

    const float4* anchors = (const float4*)d_in[ia];
    const float4* gts     = (const float4*)d_in[ig];
    const int*    counts  = (const int*)d_in[ic];
    const int*    ua_ptr  = (iu >= 0) ? (const int*)d_in[iu] : (const int*)0;
    float* out = (float*)d_out;

    const int B = in_sizes[ic];
    const int A = in_sizes[ig] / (4 * B);
    const int N = in_sizes[ia] / (4 * B);

    const int anchorsPerBlock = TPB * RPT;
    const int blocksPerBatch = (N + anchorsPerBlock - 1) / anchorsPerBlock;
    const int grid = B * blocksPerBatch;

    AssignClsLabel_kernel<<<grid, TPB>>>(anchors, gts, counts, ua_ptr, out,
                                         N, A, blocksPerBatch);
}

// round 17
// speedup vs baseline: 1.0582x; 1.0582x over previous
#include <cuda_runtime.h>
#include <cuda_bf16.h>

#define TPB 128        // measured optimum (256=29.7, 128=29.4, 64=30.8)
#define RPT 4          // anchors per thread
#define MAXA 256       // smem GT capacity (A=64 here; +1 pad slot used)

__global__ __launch_bounds__(TPB)
void AssignClsLabel_kernel(const float4* __restrict__ anchors,
                           const float4* __restrict__ gts,
                           const int* __restrict__ counts,
                           const int* __restrict__ use_anchor_p,
                           float* __restrict__ out,
                           int N, int A, int blocksPerBatch) {
    __shared__ float4 sg4[MAXA + 1];   // compacted (gy1, gx1, gy2, gx2) + pad
    __shared__ float  sga[MAXA + 1];   // compacted gt area + pad
    __shared__ float  sredmax[TPB / 32], sredmin[TPB / 32];
    __shared__ int    scnt;

    const int b   = blockIdx.x / blocksPerBatch;
    const int blk = blockIdx.x - b * blocksPerBatch;
    const int cnt = counts[b];
    const int ua  = use_anchor_p ? use_anchor_p[0] : 1;
    const int tid = threadIdx.x;
    const int base = blk * (TPB * RPT) + tid;

    // ---- Load anchors, derive corners + area (bit-identical to reference) ----
    float y1[RPT], y2[RPT], x1[RPT], x2[RPT], ar[RPT];
    float amax = -1e30f, amin = 1e30f;
    #pragma unroll
    for (int r = 0; r < RPT; r++) {
        int idx = base + r * TPB;
        // OOB sentinel: never overlaps, never positive, never in band.
        y1[r] = 4e9f; y2[r] = 4e9f; x1[r] = 4e9f; x2[r] = 4e9f; ar[r] = 1.f;
        if (idx < N) {
            float4 a = anchors[(size_t)b * N + idx];
            if (ua) {
                y1[r] = a.x - 0.5f * a.z;   // 0.5*h exact => contraction-safe
                y2[r] = y1[r] + a.z;
                x1[r] = a.y - 0.5f * a.w;
                x2[r] = x1[r] + a.w;
                ar[r] = __fmul_rn(a.z, a.w);
            } else {
                y1[r] = a.x; x1[r] = a.y; y2[r] = a.z; x2[r] = a.w;
                ar[r] = __fmul_rn(__fsub_rn(a.z, a.x), __fsub_rn(a.w, a.y));
            }
            amax = fmaxf(amax, ar[r]);
            amin = fminf(amin, ar[r]);
        }
    }

    // ---- Block-wide anchor-area min/max for exact GT pruning ----
    #pragma unroll
    for (int off = 16; off > 0; off >>= 1) {
        amax = fmaxf(amax, __shfl_xor_sync(0xffffffffu, amax, off));
        amin = fminf(amin, __shfl_xor_sync(0xffffffffu, amin, off));
    }
    if ((tid & 31) == 0) { sredmax[tid >> 5] = amax; sredmin[tid >> 5] = amin; }
    if (tid == 0) scnt = 0;
    __syncthreads();
    amax = sredmax[0]; amin = sredmin[0];
    #pragma unroll
    for (int w = 1; w < TPB / 32; w++) {
        amax = fmaxf(amax, sredmax[w]);
        amin = fminf(amin, sredmin[w]);
    }
    // iou>=0.5 requires area/2 <= ga <= 2*area (inter <= min(area,ga),
    // 3*inter >= area+ga). 0.5% slack >> fp rounding: prune is label-exact.
    const float gaHi = 2.01f * amax;
    const float gaLo = amin * (1.0f / 2.01f);

    // ---- Stage + compact valid, matchable GTs into smem ----
    for (int g = tid; g < cnt; g += TPB) {
        float4 v = gts[(size_t)b * A + g];
        float ga = __fmul_rn(__fsub_rn(v.z, v.x), __fsub_rn(v.w, v.y));
        if (ga <= gaHi && ga >= gaLo) {
            int p = atomicAdd(&scnt, 1);
            sg4[p] = v; sga[p] = ga;
        }
    }
    __syncthreads();
    const int m = scnt;
    // Even-pad with duplicate of GT 0: max-accumulation is idempotent,
    // so the duplicate cannot change any label.
    if (tid == 0 && (m & 1)) { sg4[m] = sg4[0]; sga[m] = sga[0]; }
    __syncthreads();
    const int m2 = (m + 1) & ~1;

    // ---- Main loop: identical FP body to champion; 2 GTs per trip ----
    // cond: iou>=0.5 <=> 3*inter >= ar+ga <=> w = fma(3,inter,-ga) >= ar (reals)
    float wm[RPT];
    #pragma unroll
    for (int r = 0; r < RPT; r++) wm[r] = -1e30f;

    for (int g = 0; g < m2; g += 2) {
        const float4 va  = sg4[g];
        const float  gaa = sga[g];
        const float4 vb  = sg4[g + 1];
        const float  gab = sga[g + 1];
        #pragma unroll
        for (int r = 0; r < RPT; r++) {
            // dy clamped; dx unclamped: dx<0 => inter<=0 => w<=-ga, safely negative.
            float dy    = fmaxf(0.f, __fsub_rn(fminf(y2[r], va.z), fmaxf(y1[r], va.x)));
            float dx    = __fsub_rn(fminf(x2[r], va.w), fmaxf(x1[r], va.y));
            float inter = __fmul_rn(dy, dx);            // bit-identical to ref (overlap)
            float w     = __fmaf_rn(3.0f, inter, -gaa); // single rounding
            wm[r] = fmaxf(wm[r], w);
        }
        #pragma unroll
        for (int r = 0; r < RPT; r++) {
            float dy    = fmaxf(0.f, __fsub_rn(fminf(y2[r], vb.z), fmaxf(y1[r], vb.x)));
            float dx    = __fsub_rn(fminf(x2[r], vb.w), fmaxf(x1[r], vb.y));
            float inter = __fmul_rn(dy, dx);
            float w     = __fmaf_rn(3.0f, inter, -gab);
            wm[r] = fmaxf(wm[r], w);
        }
    }

    // ---- Classify; rare band hits -> literal bit-exact fallback ----
    #pragma unroll
    for (int r = 0; r < RPT; r++) {
        int idx = base + r * TPB;
        if (idx >= N) continue;
        // band = 2^-21*(ar+gaHi): >=6x the ref-chain (uni + cr-div) slack.
        float band = 4.76837158203125e-7f * (ar[r] + gaHi);
        float lab;
        if (wm[r] >= ar[r] + band) {
            lab = 1.0f;
        } else if (wm[r] <= ar[r] - band) {
            lab = 0.0f;
        } else {
            lab = 0.0f;   // literal reference recompute over ALL valid GTs
            for (int g = 0; g < cnt; g++) {
                float4 v2 = gts[(size_t)b * A + g];
                float ga2 = __fmul_rn(__fsub_rn(v2.z, v2.x), __fsub_rn(v2.w, v2.y));
                float yy1 = fminf(fmaxf(y1[r], v2.x), v2.z);
                float yy2 = fminf(fmaxf(y2[r], v2.x), v2.z);
                float xx1 = fminf(fmaxf(x1[r], v2.y), v2.w);
                float xx2 = fminf(fmaxf(x2[r], v2.y), v2.w);
                float it  = __fmul_rn(__fsub_rn(yy2, yy1), __fsub_rn(xx2, xx1));
                float uni = __fsub_rn(__fadd_rn(ar[r], ga2), it);
                if (__fdiv_rn(it, uni) >= 0.5f) { lab = 1.0f; break; }
            }
        }
        out[(size_t)b * N + idx] = lab;
    }
}

extern "C" void kernel_launch(void* const* d_in, const int* in_sizes, int n_in,
                              void* d_out, int out_size) {
    // Bind by size signature: anchors = largest; gts = 2nd largest;
    // of the rest, counts = larger (B elems), use_anchor = smaller (optional).
    int ia = 0;
    for (int i = 1; i < n_in; i++) if (in_sizes[i] > in_sizes[ia]) ia = i;
    int ig = -1;
    for (int i = 0; i < n_in; i++) {
        if (i == ia) continue;
        if (ig < 0 || in_sizes[i] > in_sizes[ig]) ig = i;
    }
    int ic = -1, iu = -1;
    for (int i = 0; i < n_in; i++) {
        if (i == ia || i == ig) continue;
        if (ic < 0) ic = i;
        else if (in_sizes[i] > in_sizes[ic]) { iu = ic; ic = i; }
        else iu = i;
    }

    const float4* anchors = (const float4*)d_in[ia];
    const float4* gts     = (const float4*)d_in[ig];
    const int*    counts  = (const int*)d_in[ic];
    const int*    ua_ptr  = (iu >= 0) ? (const int*)d_in[iu] : (const int*)0;
    float* out = (float*)d_out;

    const int B = in_sizes[ic];
    const int A = in_sizes[ig] / (4 * B);
    const int N = in_sizes[ia] / (4 * B);

    const int anchorsPerBlock = TPB * RPT;
    const int blocksPerBatch = (N + anchorsPerBlock - 1) / anchorsPerBlock;
    const int grid = B * blocksPerBatch;

    AssignClsLabel_kernel<<<grid, TPB>>>(anchors, gts, counts, ua_ptr, out,
                                         N, A, blocksPerBatch);
}